// round 11
// baseline (speedup 1.0000x reference)
#include <cuda_runtime.h>
#include <cuda_bf16.h>

#define BB 1024
#define NN 8192
#define KK 4096
#define BN (BB * NN)

// Scratch: pos_map[n] = k if n == info_set[k] else -1
__device__ __align__(16) int g_posmap[NN];

// Single setup kernel: binary search (lower_bound) over sorted info_set.
__global__ void k_build_posmap(const int* __restrict__ info_set) {
    int n = blockIdx.x * blockDim.x + threadIdx.x;
    int lo = 0, hi = KK;
    #pragma unroll
    for (int s = 0; s < 13; s++) {            // ceil(log2(4096)) = 12, 13 is safe
        if (lo >= hi) break;
        int mid = (lo + hi) >> 1;
        if (__ldg(&info_set[mid]) < n) lo = mid + 1; else hi = mid;
    }
    g_posmap[n] = (lo < KK && __ldg(&info_set[lo]) == n) ? lo : -1;
}

// Spread 8 bits to every 4th bit position (Morton-style).
__device__ __forceinline__ unsigned spread4(unsigned x) {
    x = (x | (x << 12)) & 0x000F000Fu;
    x = (x | (x << 6))  & 0x03030303u;
    x = (x | (x << 3))  & 0x11111111u;
    return x;
}

// One block per batch row, 256 threads.
// Phase 1: each thread owns 4 consecutive n (int4/float4 I/O); writes f,u,p,r
//          and ballot-packs u bits (4 ballots + interleave) into 256 words.
// Phase 2: GF(2) superset-sum word stages in smem (strides 1..128).
// Phase 3: x[o] = y[rev13(o)] -> per thread 4 smem words, 8 float4 stores.
__global__ __launch_bounds__(256) void k_polar_main(
    const float* __restrict__ info_bits,
    const int*   __restrict__ u_random,
    float*       __restrict__ out)
{
    __shared__ unsigned sw[256];

    const int b    = blockIdx.x;
    const int t    = threadIdx.x;
    const int lane = t & 31;
    const int warp = t >> 5;

    const int4*  ur4    = (const int4*)(u_random + (long long)b * NN);
    const int4*  pm4    = (const int4*)g_posmap;
    const float* ib_row = info_bits + (long long)b * KK;

    float4* x4 = (float4*)(out);
    float4* f4 = (float4*)(out + (long long)BN);
    float4* u4 = (float4*)(out + 2LL * BN);
    float4* p4 = (float4*)(out + 3LL * BN);
    float4* r4 = (float4*)(out + 5LL * BN);

    const int  base4  = b * 2048;   // float4 index of row start (N/4)
    const int  base8  = b * 4096;   // float4 index for 2-wide sections (2N/4)
    const int  w      = lane & 3;   // which word of the 128-bit warp chunk

    // ---- Phase 1 ----
    #pragma unroll
    for (int i = 0; i < 8; i++) {
        int idx4 = i * 256 + t;                 // n = 4*idx4
        int4 ur = __ldcs(&ur4[idx4]);
        int4 pm = pm4[idx4];

        int uvx = ur.x, fvx = ur.x;
        int uvy = ur.y, fvy = ur.y;
        int uvz = ur.z, fvz = ur.z;
        int uvw = ur.w, fvw = ur.w;
        if (pm.x >= 0) { uvx = __ldcs(&ib_row[pm.x]) > 0.5f; fvx = 2; }
        if (pm.y >= 0) { uvy = __ldcs(&ib_row[pm.y]) > 0.5f; fvy = 2; }
        if (pm.z >= 0) { uvz = __ldcs(&ib_row[pm.z]) > 0.5f; fvz = 2; }
        if (pm.w >= 0) { uvw = __ldcs(&ib_row[pm.w]) > 0.5f; fvw = 2; }

        __stcs(&f4[base4 + idx4], make_float4((float)fvx, (float)fvy, (float)fvz, (float)fvw));
        __stcs(&u4[base4 + idx4], make_float4((float)uvx, (float)uvy, (float)uvz, (float)uvw));
        __stcs(&p4[base8 + idx4 * 2],     make_float4(0.5f, 0.5f, 0.5f, 0.5f));
        __stcs(&p4[base8 + idx4 * 2 + 1], make_float4(0.5f, 0.5f, 0.5f, 0.5f));
        __stcs(&r4[base8 + idx4 * 2],
               make_float4((float)(1 - ur.x), (float)ur.x, (float)(1 - ur.y), (float)ur.y));
        __stcs(&r4[base8 + idx4 * 2 + 1],
               make_float4((float)(1 - ur.z), (float)ur.z, (float)(1 - ur.w), (float)ur.w));

        // pack 4 bits/thread -> 4 words per warp (128 consecutive n)
        unsigned nib = (unsigned)uvx | ((unsigned)uvy << 1) |
                       ((unsigned)uvz << 2) | ((unsigned)uvw << 3);
        unsigned b0 = __ballot_sync(0xFFFFFFFFu, nib & 1u);
        unsigned b1 = __ballot_sync(0xFFFFFFFFu, nib & 2u);
        unsigned b2 = __ballot_sync(0xFFFFFFFFu, nib & 4u);
        unsigned b3 = __ballot_sync(0xFFFFFFFFu, nib & 8u);

        unsigned word = spread4((b0 >> (8 * w)) & 0xFFu)
                      | (spread4((b1 >> (8 * w)) & 0xFFu) << 1)
                      | (spread4((b2 >> (8 * w)) & 0xFFu) << 2)
                      | (spread4((b3 >> (8 * w)) & 0xFFu) << 3);

        // in-word superset-sum stages (n-bits 0..4)
        word ^= (word >> 1)  & 0x55555555u;
        word ^= (word >> 2)  & 0x33333333u;
        word ^= (word >> 4)  & 0x0F0F0F0Fu;
        word ^= (word >> 8)  & 0x00FF00FFu;
        word ^= (word >> 16) & 0x0000FFFFu;

        if (lane < 4) sw[i * 32 + warp * 4 + w] = word;
    }
    __syncthreads();

    // ---- Phase 2: word-level superset-sum (n-bits 5..12) ----
    #pragma unroll
    for (int s = 1; s < 256; s <<= 1) {
        unsigned v = 0u;
        bool act = (t & s) == 0;
        if (act) v = sw[t + s];
        if (act) sw[t] ^= v;
        __syncthreads();
    }

    // ---- Phase 3: bit-reversed unpack, float4 stores ----
    // n = m*1024 + 4t + c ; word = sw[rev2(c)*64 + rev6(t&63)] ; bit = rev5(n>>8)
    int t6 = (int)(__brev((unsigned)(t & 63)) >> 26);
    unsigned w0 = sw[t6];          // c=0
    unsigned w1 = sw[128 + t6];    // c=1 (rev2(1)=2)
    unsigned w2 = sw[64 + t6];     // c=2 (rev2(2)=1)
    unsigned w3 = sw[192 + t6];    // c=3
    int ihi = t >> 6;
    #pragma unroll
    for (int m = 0; m < 8; m++) {
        int bit = (int)(__brev((unsigned)(4 * m + ihi)) >> 27);  // rev5(i)
        float4 v;
        v.x = (float)((w0 >> bit) & 1u);
        v.y = (float)((w1 >> bit) & 1u);
        v.z = (float)((w2 >> bit) & 1u);
        v.w = (float)((w3 >> bit) & 1u);
        __stcs(&x4[base4 + m * 256 + t], v);
    }
}

extern "C" void kernel_launch(void* const* d_in, const int* in_sizes, int n_in,
                              void* d_out, int out_size) {
    const float* info_bits = (const float*)d_in[0];  // (B, K) float32 0/1
    const int*   u_random  = (const int*)d_in[1];    // (B, N) int32 0/1
    const int*   info_set  = (const int*)d_in[2];    // (K,) sorted int32
    float* out = (float*)d_out;                      // 7*B*N float32

    k_build_posmap<<<NN / 256, 256>>>(info_set);
    k_polar_main<<<BB, 256>>>(info_bits, u_random, out);
}

// round 12
// speedup vs baseline: 1.2655x; 1.2655x over previous
#include <cuda_runtime.h>
#include <cuda_bf16.h>

#define BB 1024
#define NN 8192
#define KK 4096
#define BN (BB * NN)

// Single fused kernel. One block per batch row, 256 threads.
//
// Phase A: stream u_random once: write r (float2) and p (float2), ballot-pack
//          the 8192 u_random bits into a 256-word smem bitset ub[].
// Phase B: scatter info bits: k strided over info_set (coalesced); set/clear
//          bit n=info_set[k] in ub[] via smem atomics, mark frozen[] bit.
// Phase C: write u and f from the final bitsets (scalar coalesced stores).
// Phase D: GF(2) superset-sum (zeta) transform: y[j] = XOR_{p superset j} u[p]
//          -> 5 in-word xor-shift stages + 8 word-stride smem stages.
// Phase E: x[o] = y[rev13(o)]: with o = i*256+t, that is bit rev5(i) of word
//          rev8(t) -> one smem word per thread, 32 coalesced scalar stores.
__global__ __launch_bounds__(256) void k_polar_fused(
    const float* __restrict__ info_bits,
    const int*   __restrict__ u_random,
    const int*   __restrict__ info_set,
    float*       __restrict__ out)
{
    __shared__ unsigned ub[256];   // u bitset, word w holds n in [32w, 32w+32)
    __shared__ unsigned fz[256];   // frozen bitset (info positions)

    const int b    = blockIdx.x;
    const int t    = threadIdx.x;
    const int lane = t & 31;
    const int warp = t >> 5;

    const int*   ur_row = u_random  + b * NN;
    const float* ib_row = info_bits + b * KK;

    float*  out_x = out;
    float*  out_f = out + (long long)BN;
    float*  out_u = out + 2LL * BN;
    float2* out_p = (float2*)(out + 3LL * BN);
    float2* out_r = (float2*)(out + 5LL * BN);

    const int rowbase = b * NN;

    fz[t] = 0u;

    // ---- Phase A: p, r outputs + ballot pack of u_random ----
    #pragma unroll 4
    for (int i = 0; i < 32; i++) {
        int n  = i * 256 + t;
        int ur = ur_row[n];
        int idx = rowbase + n;
        out_p[idx] = make_float2(0.5f, 0.5f);
        out_r[idx] = make_float2((float)(1 - ur), (float)ur);
        unsigned bal = __ballot_sync(0xFFFFFFFFu, ur);
        if (lane == 0) ub[i * 8 + warp] = bal;     // word index = n>>5
    }
    __syncthreads();

    // ---- Phase B: scatter info bits into the bitsets (smem atomics) ----
    #pragma unroll
    for (int k = t; k < KK; k += 256) {
        int n = info_set[k];                        // coalesced, L2-broadcast
        int w = n >> 5;
        unsigned m = 1u << (n & 31);
        atomicOr(&fz[w], m);
        if (ib_row[k] > 0.5f) atomicOr(&ub[w], m);  // coalesced read
        else                  atomicAnd(&ub[w], ~m);
    }
    __syncthreads();

    // ---- Phase C: u, f outputs from final bitsets ----
    #pragma unroll 4
    for (int i = 0; i < 32; i++) {
        int n  = i * 256 + t;
        unsigned wu = ub[i * 8 + warp];             // LDS broadcast
        unsigned wf = fz[i * 8 + warp];
        int uv = (int)((wu >> lane) & 1u);
        int fv = ((wf >> lane) & 1u) ? 2 : uv;
        int idx = rowbase + n;
        out_u[idx] = (float)uv;
        out_f[idx] = (float)fv;
    }

    // ---- Phase D: superset-sum transform ----
    unsigned W = ub[t];
    __syncthreads();                                // all Phase-C reads done

    // in-word stages (n-bits 0..4): y[j] ^= y[j + 2^s] where bit s clear
    W ^= (W >> 1)  & 0x55555555u;
    W ^= (W >> 2)  & 0x33333333u;
    W ^= (W >> 4)  & 0x0F0F0F0Fu;
    W ^= (W >> 8)  & 0x00FF00FFu;
    W ^= (W >> 16) & 0x0000FFFFu;
    ub[t] = W;
    __syncthreads();

    // word-level stages (n-bits 5..12, strides 1..128). Writers are bit-clear
    // positions; they read only bit-set positions (never written this stage),
    // so one sync per stage suffices.
    #pragma unroll
    for (int s = 1; s < 256; s <<= 1) {
        unsigned v = 0u;
        bool act = (t & s) == 0;
        if (act) v = ub[t + s];
        if (act) ub[t] ^= v;
        __syncthreads();
    }

    // ---- Phase E: bit-reversed unpack, coalesced scalar stores ----
    unsigned Wr = ub[__brev((unsigned)t) >> 24];    // word rev8(t)
    #pragma unroll
    for (int i = 0; i < 32; i++) {
        int bit = (int)(__brev((unsigned)i) >> 27); // rev5(i)
        out_x[rowbase + i * 256 + t] = (float)((Wr >> bit) & 1u);
    }
}

extern "C" void kernel_launch(void* const* d_in, const int* in_sizes, int n_in,
                              void* d_out, int out_size) {
    const float* info_bits = (const float*)d_in[0];  // (B, K) float32 0/1
    const int*   u_random  = (const int*)d_in[1];    // (B, N) int32 0/1
    const int*   info_set  = (const int*)d_in[2];    // (K,) sorted int32
    float* out = (float*)d_out;                      // 7*B*N float32

    k_polar_fused<<<BB, 256>>>(info_bits, u_random, info_set, out);
}

// round 16
// speedup vs baseline: 1.4229x; 1.1243x over previous
#include <cuda_runtime.h>
#include <cuda_bf16.h>

#define BB 1024
#define NN 8192
#define KK 4096
#define BN (BB * NN)

// Frozen-position bitmask: bit (n&31) of word n>>5 set iff n is in info_set.
__device__ unsigned g_fm[256];

// Setup: 32 blocks x 256 threads. Binary search membership, ballot-pack.
__global__ void k_build_fm(const int* __restrict__ info_set) {
    int n = blockIdx.x * blockDim.x + threadIdx.x;
    int lo = 0, hi = KK;
    #pragma unroll 1
    while (lo < hi) {
        int mid = (lo + hi) >> 1;
        if (__ldg(&info_set[mid]) < n) lo = mid + 1; else hi = mid;
    }
    bool found = (lo < KK) && (__ldg(&info_set[lo]) == n);
    unsigned bal = __ballot_sync(0xFFFFFFFFu, found);
    if ((threadIdx.x & 31) == 0) g_fm[n >> 5] = bal;
}

// Main: one block per batch row, 256 threads.
// Prologue: load FM, block-scan popcounts -> pfx[w] = #frozen positions < 32w.
//           (info_set sorted => rank of a frozen position n == its index k
//            into info_bits, so k = pfx[w] + popc(FM[w] & lanemask_lt).)
// Phase 1:  stream the row once: write f,u (scalar), p,r (float2), and
//           ballot-pack u into a 256-word smem bitset with the in-word
//           superset-sum stages folded in.
// Phase 2:  word-level GF(2) superset-sum stages (strides 1..128).
// Phase 3:  x[o] = y[rev13(o)]: bit rev5(i) of word rev8(t); coalesced stores.
__global__ __launch_bounds__(256) void k_polar_main(
    const float* __restrict__ info_bits,
    const int*   __restrict__ u_random,
    float*       __restrict__ out)
{
    __shared__ unsigned sw[256];
    __shared__ unsigned fm[256];
    __shared__ int      pfx[256];
    __shared__ int      wsum[8];

    const int b    = blockIdx.x;
    const int t    = threadIdx.x;
    const int lane = t & 31;
    const int warp = t >> 5;

    const int*   ur_row = u_random  + b * NN;
    const float* ib_row = info_bits + b * KK;

    float*  out_x = out;
    float*  out_f = out + (long long)BN;
    float*  out_u = out + 2LL * BN;
    float2* out_p = (float2*)(out + 3LL * BN);
    float2* out_r = (float2*)(out + 5LL * BN);

    const int rowbase = b * NN;

    // ---- Prologue: FM + popcount prefix ----
    unsigned fmw = g_fm[t];
    fm[t] = fmw;
    int c = __popc(fmw);
    int v = c;
    #pragma unroll
    for (int d = 1; d < 32; d <<= 1) {
        int o = __shfl_up_sync(0xFFFFFFFFu, v, d);
        if (lane >= d) v += o;
    }
    if (lane == 31) wsum[warp] = v;
    __syncthreads();
    if (t == 0) {
        int a = 0;
        #pragma unroll
        for (int j = 0; j < 8; j++) { int x = wsum[j]; wsum[j] = a; a += x; }
    }
    __syncthreads();
    pfx[t] = v - c + wsum[warp];   // exclusive prefix over words
    __syncthreads();

    // ---- Phase 1: outputs + bit packing ----
    #pragma unroll 4
    for (int i = 0; i < 32; i++) {
        int n  = i * 256 + t;
        int w8 = i * 8 + warp;               // word index = n>>5
        unsigned FMw = fm[w8];               // LDS broadcast
        int ur = ur_row[n];
        int uv = ur, fv = ur;
        if ((FMw >> lane) & 1u) {
            int k = pfx[w8] + __popc(FMw & ((1u << lane) - 1u));
            uv = (ib_row[k] > 0.5f) ? 1 : 0; // active lanes: consecutive k
            fv = 2;
        }
        int idx = rowbase + n;
        out_f[idx] = (float)fv;
        out_u[idx] = (float)uv;
        out_p[idx] = make_float2(0.5f, 0.5f);
        out_r[idx] = make_float2((float)(1 - ur), (float)ur);

        unsigned bal = __ballot_sync(0xFFFFFFFFu, uv);
        // in-word superset-sum stages (n-bits 0..4)
        bal ^= (bal >> 1)  & 0x55555555u;
        bal ^= (bal >> 2)  & 0x33333333u;
        bal ^= (bal >> 4)  & 0x0F0F0F0Fu;
        bal ^= (bal >> 8)  & 0x00FF00FFu;
        bal ^= (bal >> 16) & 0x0000FFFFu;
        if (lane == 0) sw[w8] = bal;
    }
    __syncthreads();

    // ---- Phase 2: word-level stages (n-bits 5..12, strides 1..128) ----
    // Writers are bit-clear positions reading bit-set positions (never
    // written this stage) -> one sync per stage suffices.
    #pragma unroll
    for (int s = 1; s < 256; s <<= 1) {
        unsigned vv = 0u;
        bool act = (t & s) == 0;
        if (act) vv = sw[t + s];
        if (act) sw[t] ^= vv;
        __syncthreads();
    }

    // ---- Phase 3: bit-reversed unpack, coalesced scalar stores ----
    unsigned W = sw[__brev((unsigned)t) >> 24];     // word rev8(t)
    #pragma unroll
    for (int i = 0; i < 32; i++) {
        int bit = (int)(__brev((unsigned)i) >> 27); // rev5(i)
        out_x[rowbase + i * 256 + t] = (float)((W >> bit) & 1u);
    }
}

extern "C" void kernel_launch(void* const* d_in, const int* in_sizes, int n_in,
                              void* d_out, int out_size) {
    const float* info_bits = (const float*)d_in[0];  // (B, K) float32 0/1
    const int*   u_random  = (const int*)d_in[1];    // (B, N) int32 0/1
    const int*   info_set  = (const int*)d_in[2];    // (K,) sorted int32
    float* out = (float*)d_out;                      // 7*B*N float32

    k_build_fm<<<NN / 256, 256>>>(info_set);
    k_polar_main<<<BB, 256>>>(info_bits, u_random, out);
}